// round 15
// baseline (speedup 1.0000x reference)
#include <cuda_runtime.h>
#include <math.h>
#include <stdint.h>

#define N_NODES 8192
#define E_RAW   262144
#define E_TOT   (E_RAW + N_NODES)   /* 270336: edges + self loops */
#define IN_CHN  256
#define CHN     128
#define SLOPE   0.2f

/* ------------------------------------------------------------------ */
/* Device scratch (static — no allocation allowed)                     */
/* ------------------------------------------------------------------ */
__device__ int   g_nonzero;                 /* dtype detect flag        */
__device__ int   g_deg[N_NODES];
__device__ int   g_off[N_NODES + 1];
__device__ int   g_cursor[N_NODES];
__device__ int   g_srcraw[E_TOT];
__device__ int   g_dstraw[E_TOT];
__device__ int   g_srcsort[E_TOT];          /* src ids sorted by dst    */

__device__ float g_xl[N_NODES * 256];
__device__ float g_xr[N_NODES * 256];
__device__ float g_h [N_NODES * CHN];
__device__ float g_z [N_NODES * 2 * CHN];
__device__ float g_re[N_NODES * CHN];
__device__ float g_xd[N_NODES * CHN];

/* ------------------------------------------------------------------ */
/* Host-side stream/event resources (static init; host objects only)   */
/* ------------------------------------------------------------------ */
struct GpuRes {
    cudaStream_t s2;
    cudaEvent_t  ev_fork1, ev_csr, ev_fork2, ev_recon;
    GpuRes() {
        cudaStreamCreateWithFlags(&s2, cudaStreamNonBlocking);
        cudaEventCreateWithFlags(&ev_fork1, cudaEventDisableTiming);
        cudaEventCreateWithFlags(&ev_csr,   cudaEventDisableTiming);
        cudaEventCreateWithFlags(&ev_fork2, cudaEventDisableTiming);
        cudaEventCreateWithFlags(&ev_recon, cudaEventDisableTiming);
    }
};
static GpuRes g_res;

/* ------------------------------------------------------------------ */
/* mma.sync helpers                                                    */
/* ------------------------------------------------------------------ */
__device__ __forceinline__ uint32_t cvt_tf32(float x)
{
    uint32_t o;
    asm("cvt.rna.tf32.f32 %0, %1;" : "=r"(o) : "f"(x));
    return o;
}

__device__ __forceinline__ void mma_tf32(float* d,
                                         const uint32_t* a,
                                         const uint32_t* b)
{
    asm volatile(
        "mma.sync.aligned.m16n8k8.row.col.f32.tf32.tf32.f32 "
        "{%0,%1,%2,%3}, {%4,%5,%6,%7}, {%8,%9}, {%0,%1,%2,%3};"
        : "+f"(d[0]), "+f"(d[1]), "+f"(d[2]), "+f"(d[3])
        : "r"(a[0]), "r"(a[1]), "r"(a[2]), "r"(a[3]),
          "r"(b[0]), "r"(b[1]));
}

/* ------------------------------------------------------------------ */
/* Preprocessing: CSR build                                            */
/* ------------------------------------------------------------------ */
__global__ void k_pre0(const unsigned int* w)
{
    int t = threadIdx.x;              /* 256 threads */
    if (t == 0) g_nonzero = 0;
#pragma unroll
    for (int i = 0; i < 8; i++)
        *(int4*)(g_deg + t * 32 + i * 4) = make_int4(0, 0, 0, 0);
    __syncthreads();
    unsigned acc = 0;
#pragma unroll
    for (int i = 0; i < 16; i++)
        acc |= w[2 * (t * 16 + i) + 1];
    if (acc) atomicOr(&g_nonzero, 1);
}

__global__ void k_extract(const void* ei_raw)
{
    int i = blockIdx.x * blockDim.x + threadIdx.x;
    if (i >= E_TOT) return;
    int s, d;
    if (i < E_RAW) {
        if (g_nonzero == 0) {   /* int64 */
            const long long* e = (const long long*)ei_raw;
            s = (int)e[i];
            d = (int)e[E_RAW + i];
        } else {                /* int32 */
            const int* e = (const int*)ei_raw;
            s = e[i];
            d = e[E_RAW + i];
        }
    } else {                    /* self loop */
        s = i - E_RAW;
        d = s;
    }
    g_srcraw[i] = s;
    g_dstraw[i] = d;
    atomicAdd(&g_deg[d], 1);
}

/* 1 block x 256 threads; warp-shuffle scan */
__global__ void k_scan()
{
    __shared__ int ws[8];
    int t = threadIdx.x;
    int lane = t & 31, w = t >> 5;

    int4 loc[8];
    int sum = 0;
#pragma unroll
    for (int i = 0; i < 8; i++) {
        loc[i] = *(const int4*)(g_deg + t * 32 + i * 4);
        sum += loc[i].x + loc[i].y + loc[i].z + loc[i].w;
    }
    int inc = sum;
#pragma unroll
    for (int o = 1; o < 32; o <<= 1) {
        int v = __shfl_up_sync(0xffffffffu, inc, o);
        if (lane >= o) inc += v;
    }
    if (lane == 31) ws[w] = inc;
    __syncthreads();
    if (w == 0) {
        int x = (lane < 8) ? ws[lane] : 0;
#pragma unroll
        for (int o = 1; o < 8; o <<= 1) {
            int v = __shfl_up_sync(0xffffffffu, x, o);
            if (lane >= o) x += v;
        }
        if (lane < 8) ws[lane] = x;
    }
    __syncthreads();

    int run = inc - sum + (w > 0 ? ws[w - 1] : 0);
#pragma unroll
    for (int i = 0; i < 8; i++) {
        int4 d = loc[i];
        int4 o;
        o.x = run;            run += d.x;
        o.y = run;            run += d.y;
        o.z = run;            run += d.z;
        o.w = run;            run += d.w;
        *(int4*)(g_off    + t * 32 + i * 4) = o;
        *(int4*)(g_cursor + t * 32 + i * 4) = o;
    }
    if (t == 255) g_off[N_NODES] = ws[7];
}

__global__ void k_scatter()
{
    int i = blockIdx.x * blockDim.x + threadIdx.x;
    if (i >= E_TOT) return;
    int d = g_dstraw[i];
    int p = atomicAdd(&g_cursor[d], 1);
    g_srcsort[p] = g_srcraw[i];
}

/* ------------------------------------------------------------------ */
/* Dual GEMM via mma.sync tf32 + 3xTF32 compensation (fp32 accuracy).  */
/* ------------------------------------------------------------------ */
#define GS 68
#define GD_SMEM (512 * GS * 4)

__global__ void __launch_bounds__(256, 1)
k_gemm_dual_mma(const float* __restrict__ X,
                const float* __restrict__ Wl,
                const float* __restrict__ Wr,
                float* __restrict__ XL,
                float* __restrict__ XR,
                int K, int OC)
{
    extern __shared__ float sm[];
    float* Ah  = sm;
    float* Al  = Ah  + 128 * GS;
    float* Blh = Al  + 128 * GS;
    float* Bll = Blh + 64 * GS;
    float* Brh = Bll + 64 * GS;
    float* Brl = Brh + 64 * GS;

    int tid = threadIdx.x;
    int wid = tid >> 5, lane = tid & 31;
    int m0 = blockIdx.x * 128, n0 = blockIdx.y * 64;
    int wm = (wid & 3) * 32;
    int wn = (wid >> 2) * 32;
    int fr = lane >> 2, fc = lane & 3;

    float accL[2][4][4], accR[2][4][4];
#pragma unroll
    for (int mt = 0; mt < 2; mt++)
#pragma unroll
        for (int nt = 0; nt < 4; nt++)
#pragma unroll
            for (int e = 0; e < 4; e++) { accL[mt][nt][e] = 0.0f; accR[mt][nt][e] = 0.0f; }

    for (int k0 = 0; k0 < K; k0 += 64) {
#pragma unroll
        for (int it = 0; it < 8; it++) {
            int f = it * 256 + tid;
            int r = f >> 4, q = f & 15;
            float4 v = *(const float4*)(X + (size_t)(m0 + r) * K + k0 + q * 4);
            uint32_t h0 = cvt_tf32(v.x), h1 = cvt_tf32(v.y);
            uint32_t h2 = cvt_tf32(v.z), h3 = cvt_tf32(v.w);
            uint32_t* dh = (uint32_t*)(Ah + r * GS + q * 4);
            uint32_t* dl = (uint32_t*)(Al + r * GS + q * 4);
            dh[0] = h0; dh[1] = h1; dh[2] = h2; dh[3] = h3;
            dl[0] = cvt_tf32(v.x - __uint_as_float(h0));
            dl[1] = cvt_tf32(v.y - __uint_as_float(h1));
            dl[2] = cvt_tf32(v.z - __uint_as_float(h2));
            dl[3] = cvt_tf32(v.w - __uint_as_float(h3));
        }
#pragma unroll
        for (int it = 0; it < 4; it++) {
            int f = it * 256 + tid;
            int r = f >> 4, q = f & 15;
            float4 v = *(const float4*)(Wl + (size_t)(n0 + r) * K + k0 + q * 4);
            uint32_t h0 = cvt_tf32(v.x), h1 = cvt_tf32(v.y);
            uint32_t h2 = cvt_tf32(v.z), h3 = cvt_tf32(v.w);
            uint32_t* dh = (uint32_t*)(Blh + r * GS + q * 4);
            uint32_t* dl = (uint32_t*)(Bll + r * GS + q * 4);
            dh[0] = h0; dh[1] = h1; dh[2] = h2; dh[3] = h3;
            dl[0] = cvt_tf32(v.x - __uint_as_float(h0));
            dl[1] = cvt_tf32(v.y - __uint_as_float(h1));
            dl[2] = cvt_tf32(v.z - __uint_as_float(h2));
            dl[3] = cvt_tf32(v.w - __uint_as_float(h3));

            v = *(const float4*)(Wr + (size_t)(n0 + r) * K + k0 + q * 4);
            h0 = cvt_tf32(v.x); h1 = cvt_tf32(v.y);
            h2 = cvt_tf32(v.z); h3 = cvt_tf32(v.w);
            dh = (uint32_t*)(Brh + r * GS + q * 4);
            dl = (uint32_t*)(Brl + r * GS + q * 4);
            dh[0] = h0; dh[1] = h1; dh[2] = h2; dh[3] = h3;
            dl[0] = cvt_tf32(v.x - __uint_as_float(h0));
            dl[1] = cvt_tf32(v.y - __uint_as_float(h1));
            dl[2] = cvt_tf32(v.z - __uint_as_float(h2));
            dl[3] = cvt_tf32(v.w - __uint_as_float(h3));
        }
        __syncthreads();

        const uint32_t* Ahu  = (const uint32_t*)Ah;
        const uint32_t* Alu  = (const uint32_t*)Al;
        const uint32_t* Blhu = (const uint32_t*)Blh;
        const uint32_t* Bllu = (const uint32_t*)Bll;
        const uint32_t* Brhu = (const uint32_t*)Brh;
        const uint32_t* Brlu = (const uint32_t*)Brl;

#pragma unroll
        for (int ks = 0; ks < 64; ks += 8) {
            uint32_t ah[2][4], al[2][4];
#pragma unroll
            for (int mt = 0; mt < 2; mt++) {
                int row = wm + mt * 16 + fr;
                ah[mt][0] = Ahu[row * GS + ks + fc];
                ah[mt][1] = Ahu[(row + 8) * GS + ks + fc];
                ah[mt][2] = Ahu[row * GS + ks + 4 + fc];
                ah[mt][3] = Ahu[(row + 8) * GS + ks + 4 + fc];
                al[mt][0] = Alu[row * GS + ks + fc];
                al[mt][1] = Alu[(row + 8) * GS + ks + fc];
                al[mt][2] = Alu[row * GS + ks + 4 + fc];
                al[mt][3] = Alu[(row + 8) * GS + ks + 4 + fc];
            }
            uint32_t blh[4][2], bll[4][2], brh[4][2], brl[4][2];
#pragma unroll
            for (int nt = 0; nt < 4; nt++) {
                int n = wn + nt * 8 + fr;
                blh[nt][0] = Blhu[n * GS + ks + fc];
                blh[nt][1] = Blhu[n * GS + ks + 4 + fc];
                bll[nt][0] = Bllu[n * GS + ks + fc];
                bll[nt][1] = Bllu[n * GS + ks + 4 + fc];
                brh[nt][0] = Brhu[n * GS + ks + fc];
                brh[nt][1] = Brhu[n * GS + ks + 4 + fc];
                brl[nt][0] = Brlu[n * GS + ks + fc];
                brl[nt][1] = Brlu[n * GS + ks + 4 + fc];
            }
#pragma unroll
            for (int mt = 0; mt < 2; mt++)
#pragma unroll
                for (int nt = 0; nt < 4; nt++) {
                    mma_tf32(accL[mt][nt], al[mt], blh[nt]);
                    mma_tf32(accL[mt][nt], ah[mt], bll[nt]);
                    mma_tf32(accL[mt][nt], ah[mt], blh[nt]);
                    mma_tf32(accR[mt][nt], al[mt], brh[nt]);
                    mma_tf32(accR[mt][nt], ah[mt], brl[nt]);
                    mma_tf32(accR[mt][nt], ah[mt], brh[nt]);
                }
        }
        __syncthreads();
    }

#pragma unroll
    for (int mt = 0; mt < 2; mt++)
#pragma unroll
        for (int nt = 0; nt < 4; nt++) {
            int row = m0 + wm + mt * 16 + fr;
            int col = n0 + wn + nt * 8 + (lane & 3) * 2;
            float* cL = accL[mt][nt];
            float* cR = accR[mt][nt];
            XL[(size_t)row * OC + col]           = cL[0];
            XL[(size_t)row * OC + col + 1]       = cL[1];
            XL[(size_t)(row + 8) * OC + col]     = cL[2];
            XL[(size_t)(row + 8) * OC + col + 1] = cL[3];
            XR[(size_t)row * OC + col]           = cR[0];
            XR[(size_t)row * OC + col + 1]       = cR[1];
            XR[(size_t)(row + 8) * OC + col]     = cR[2];
            XR[(size_t)(row + 8) * OC + col + 1] = cR[3];
        }
}

/* ------------------------------------------------------------------ */
/* GATv2 aggregation: 2 warps per node (split edge list), partial      */
/* online softmax per warp, smem merge. 256 thr = 4 nodes per CTA.     */
/* ------------------------------------------------------------------ */
__device__ __forceinline__ float warp_sum(float p)
{
#pragma unroll
    for (int o = 16; o > 0; o >>= 1) p += __shfl_xor_sync(0xffffffffu, p, o);
    return p;
}

template <int NC, int PIPE>
__global__ void k_agg2(const float* __restrict__ XL,
                       const float* __restrict__ XR,
                       const float* __restrict__ att,
                       const float* __restrict__ bias,
                       float* __restrict__ out,
                       float* __restrict__ out2)
{
    const int OC4 = NC * 32;
    __shared__ float  smv[8], ssv[8];
    __shared__ float4 sacc[8 * NC * 32];

    int warp = threadIdx.x >> 5, lane = threadIdx.x & 31;
    int v    = blockIdx.x * 4 + (warp >> 1);
    int half = warp & 1;

    const float4* XL4 = (const float4*)XL;
    const float4* XR4 = (const float4*)XR;
    const float4* at4 = (const float4*)att;
    const float4* bi4 = (const float4*)bias;

    float4 xrv[NC], atv[NC], acc[NC];
#pragma unroll
    for (int c = 0; c < NC; c++) {
        xrv[c] = XR4[v * OC4 + c * 32 + lane];
        atv[c] = at4[c * 32 + lane];
        acc[c] = make_float4(0.f, 0.f, 0.f, 0.f);
    }

    int fe0 = g_off[v], fe1 = g_off[v + 1];
    int len = fe1 - fe0;
    int mid = fe0 + ((len + 1) >> 1);
    int e0 = half ? mid : fe0;
    int e1 = half ? fe1 : mid;

    float m = -3.0e38f, s = 0.0f;
    int n4 = (e1 - e0) >> 2;

#define LK(t) ((t) > 0.0f ? (t) : SLOPE * (t))
#define DOT1(p, xv, c)                                                      \
    { float t;                                                              \
      t = xv.x + xrv[c].x; p += atv[c].x * LK(t);                           \
      t = xv.y + xrv[c].y; p += atv[c].y * LK(t);                           \
      t = xv.z + xrv[c].z; p += atv[c].z * LK(t);                           \
      t = xv.w + xrv[c].w; p += atv[c].w * LK(t); }

#define LOADB(X, base)                                                      \
    { int u0 = g_srcsort[(base)],     u1 = g_srcsort[(base) + 1];           \
      int u2 = g_srcsort[(base) + 2], u3 = g_srcsort[(base) + 3];           \
      _Pragma("unroll")                                                     \
      for (int c = 0; c < NC; c++) {                                        \
          X[0][c] = XL4[(size_t)u0 * OC4 + c * 32 + lane];                  \
          X[1][c] = XL4[(size_t)u1 * OC4 + c * 32 + lane];                  \
          X[2][c] = XL4[(size_t)u2 * OC4 + c * 32 + lane];                  \
          X[3][c] = XL4[(size_t)u3 * OC4 + c * 32 + lane];                  \
      } }

#define PROCB(X)                                                            \
    { float p0 = 0.f, p1 = 0.f, p2 = 0.f, p3 = 0.f;                         \
      _Pragma("unroll")                                                     \
      for (int c = 0; c < NC; c++) {                                        \
          DOT1(p0, X[0][c], c); DOT1(p1, X[1][c], c);                       \
          DOT1(p2, X[2][c], c); DOT1(p3, X[3][c], c);                       \
      }                                                                     \
      p0 = warp_sum(p0); p1 = warp_sum(p1);                                 \
      p2 = warp_sum(p2); p3 = warp_sum(p3);                                 \
      float bm = fmaxf(fmaxf(p0, p1), fmaxf(p2, p3));                       \
      float mn = fmaxf(m, bm);                                              \
      float sc = __expf(m - mn);                                            \
      float w0 = __expf(p0 - mn), w1 = __expf(p1 - mn);                     \
      float w2 = __expf(p2 - mn), w3 = __expf(p3 - mn);                     \
      s = s * sc + ((w0 + w1) + (w2 + w3));                                 \
      _Pragma("unroll")                                                     \
      for (int c = 0; c < NC; c++) {                                        \
          acc[c].x = acc[c].x * sc + w0 * X[0][c].x + w1 * X[1][c].x        \
                                   + w2 * X[2][c].x + w3 * X[3][c].x;       \
          acc[c].y = acc[c].y * sc + w0 * X[0][c].y + w1 * X[1][c].y        \
                                   + w2 * X[2][c].y + w3 * X[3][c].y;       \
          acc[c].z = acc[c].z * sc + w0 * X[0][c].z + w1 * X[1][c].z        \
                                   + w2 * X[2][c].z + w3 * X[3][c].z;       \
          acc[c].w = acc[c].w * sc + w0 * X[0][c].w + w1 * X[1][c].w        \
                                   + w2 * X[2][c].w + w3 * X[3][c].w;       \
      }                                                                     \
      m = mn; }

    if (PIPE) {
        float4 xA[4][NC], xB[4][NC];
        int b = 0;
        if (n4 > 0) LOADB(xA, e0);
        while (b < n4) {
            if (b + 1 < n4) LOADB(xB, e0 + (b + 1) * 4);
            PROCB(xA);
            b++;
            if (b >= n4) break;
            if (b + 1 < n4) LOADB(xA, e0 + (b + 1) * 4);
            PROCB(xB);
            b++;
        }
    } else {
        float4 xA[4][NC];
        for (int b = 0; b < n4; b++) {
            LOADB(xA, e0 + b * 4);
            PROCB(xA);
        }
    }

    for (int e = e0 + n4 * 4; e < e1; e++) {
        int u = g_srcsort[e];
        float4 xv[NC];
        float p = 0.f;
#pragma unroll
        for (int c = 0; c < NC; c++) {
            xv[c] = XL4[(size_t)u * OC4 + c * 32 + lane];
            DOT1(p, xv[c], c);
        }
        p = warp_sum(p);
        float mn = fmaxf(m, p);
        float sc = __expf(m - mn);
        float w  = __expf(p - mn);
        s = s * sc + w;
#pragma unroll
        for (int c = 0; c < NC; c++) {
            acc[c].x = acc[c].x * sc + w * xv[c].x;
            acc[c].y = acc[c].y * sc + w * xv[c].y;
            acc[c].z = acc[c].z * sc + w * xv[c].z;
            acc[c].w = acc[c].w * sc + w * xv[c].w;
        }
        m = mn;
    }
#undef DOT1
#undef LK
#undef LOADB
#undef PROCB

    /* merge the two halves via smem */
    if (lane == 0) { smv[warp] = m; ssv[warp] = s; }
#pragma unroll
    for (int c = 0; c < NC; c++)
        sacc[(warp * NC + c) * 32 + lane] = acc[c];
    __syncthreads();

    if (half == 0) {
        float mB = smv[warp + 1], sB = ssv[warp + 1];
        float mn = fmaxf(m, mB);
        float a  = __expf(m - mn);
        float b  = __expf(mB - mn);
        float inv = 1.0f / (s * a + sB * b);
#pragma unroll
        for (int c = 0; c < NC; c++) {
            float4 aB = sacc[((warp + 1) * NC + c) * 32 + lane];
            float4 b4 = bi4[c * 32 + lane];
            float4 o;
            o.x = fmaxf((acc[c].x * a + aB.x * b) * inv + b4.x, 0.0f);
            o.y = fmaxf((acc[c].y * a + aB.y * b) * inv + b4.y, 0.0f);
            o.z = fmaxf((acc[c].z * a + aB.z * b) * inv + b4.z, 0.0f);
            o.w = fmaxf((acc[c].w * a + aB.w * b) * inv + b4.w, 0.0f);
            ((float4*)out)[v * OC4 + c * 32 + lane] = o;
            if (out2) ((float4*)out2)[v * OC4 + c * 32 + lane] = o;
        }
    }
}

/* ------------------------------------------------------------------ */
/* recon = sigmoid(R @ R^T) via mma.sync tf32. 128x64 tiles, 4160     */
/* CTAs, 2 CTAs/SM. Dual-staged epilogue.                              */
/* ------------------------------------------------------------------ */
#define RSR      132
#define RC_SMEM  ((128 + 64) * RSR * 4)    /* 101376 bytes */
#define RC_NT    4160

__global__ void __launch_bounds__(256, 2)
k_recon_mma2(const float* __restrict__ R, float* __restrict__ O)
{
    extern __shared__ float smf[];
    float* As  = smf;
    float* Bs  = smf + 128 * RSR;
    float* Cs1 = As;
    float* Cs2 = Bs;

    int tid = threadIdx.x;
    int wid = tid >> 5, lane = tid & 31;

    int t = blockIdx.x;
    int p = t >> 1, hh = t & 1;
    int bj = (int)((sqrtf(8.0f * (float)p + 1.0f) - 1.0f) * 0.5f);
    while ((bj + 1) * (bj + 2) / 2 <= p) bj++;
    while (bj * (bj + 1) / 2 > p) bj--;
    int bi = p - bj * (bj + 1) / 2;
    int m0 = bi * 128;
    int n0 = bj * 128 + hh * 64;

    {
        const float4* srcA = (const float4*)(R + (size_t)m0 * CHN);
        const float4* srcB = (const float4*)(R + (size_t)n0 * CHN);
#pragma unroll
        for (int it = 0; it < 16; it++) {
            int f = it * 256 + tid;
            int r = f >> 5, q = f & 31;
            float4 va = srcA[r * 32 + q];
            uint32_t* da = (uint32_t*)(As + r * RSR + q * 4);
            da[0] = cvt_tf32(va.x); da[1] = cvt_tf32(va.y);
            da[2] = cvt_tf32(va.z); da[3] = cvt_tf32(va.w);
        }
#pragma unroll
        for (int it = 0; it < 8; it++) {
            int f = it * 256 + tid;
            int r = f >> 5, q = f & 31;
            float4 vb = srcB[r * 32 + q];
            uint32_t* db = (uint32_t*)(Bs + r * RSR + q * 4);
            db[0] = cvt_tf32(vb.x); db[1] = cvt_tf32(vb.y);
            db[2] = cvt_tf32(vb.z); db[3] = cvt_tf32(vb.w);
        }
    }
    __syncthreads();

    int wm = (wid & 3) * 32;
    int wn = (wid >> 2) * 32;
    int fr = lane >> 2, fc = lane & 3;

    float acc[2][4][4];
#pragma unroll
    for (int mt = 0; mt < 2; mt++)
#pragma unroll
        for (int nt = 0; nt < 4; nt++)
#pragma unroll
            for (int e = 0; e < 4; e++) acc[mt][nt][e] = 0.0f;

    const uint32_t* Au = (const uint32_t*)As;
    const uint32_t* Bu = (const uint32_t*)Bs;

#pragma unroll
    for (int k0 = 0; k0 < 128; k0 += 8) {
        uint32_t af[2][4];
#pragma unroll
        for (int mt = 0; mt < 2; mt++) {
            int row = wm + mt * 16 + fr;
            af[mt][0] = Au[row * RSR + k0 + fc];
            af[mt][1] = Au[(row + 8) * RSR + k0 + fc];
            af[mt][2] = Au[row * RSR + k0 + 4 + fc];
            af[mt][3] = Au[(row + 8) * RSR + k0 + 4 + fc];
        }
        uint32_t bf[4][2];
#pragma unroll
        for (int nt = 0; nt < 4; nt++) {
            int n = wn + nt * 8 + fr;
            bf[nt][0] = Bu[n * RSR + k0 + fc];
            bf[nt][1] = Bu[n * RSR + k0 + 4 + fc];
        }
#pragma unroll
        for (int mt = 0; mt < 2; mt++)
#pragma unroll
            for (int nt = 0; nt < 4; nt++)
                mma_tf32(acc[mt][nt], af[mt], bf[nt]);
    }
    __syncthreads();

#pragma unroll
    for (int mt = 0; mt < 2; mt++)
#pragma unroll
        for (int nt = 0; nt < 4; nt++) {
            int row = wm + mt * 16 + fr;
            int col = wn + nt * 8 + fc * 2;
            float* c = acc[mt][nt];
            float s0 = 1.0f / (1.0f + __expf(-c[0]));
            float s1 = 1.0f / (1.0f + __expf(-c[1]));
            float s2 = 1.0f / (1.0f + __expf(-c[2]));
            float s3 = 1.0f / (1.0f + __expf(-c[3]));
            Cs1[row * RSR + col]           = s0;
            Cs1[row * RSR + col + 1]       = s1;
            Cs1[(row + 8) * RSR + col]     = s2;
            Cs1[(row + 8) * RSR + col + 1] = s3;
            Cs2[col * RSR + row]           = s0;
            Cs2[(col + 1) * RSR + row]     = s1;
            Cs2[col * RSR + row + 8]       = s2;
            Cs2[(col + 1) * RSR + row + 8] = s3;
        }
    __syncthreads();

    {
        int c4 = (tid & 15) * 4;
        int r0 = tid >> 4;
#pragma unroll
        for (int r = r0; r < 128; r += 16) {
            float4 v = *(const float4*)(Cs1 + r * RSR + c4);
            *(float4*)(O + (size_t)(m0 + r) * N_NODES + n0 + c4) = v;
        }
    }
    {
        int c4 = (tid & 31) * 4;
        int r0 = tid >> 5;
#pragma unroll
        for (int r = r0; r < 64; r += 8) {
            float4 v = *(const float4*)(Cs2 + r * RSR + c4);
            *(float4*)(O + (size_t)(n0 + r) * N_NODES + m0 + c4) = v;
        }
    }
}

/* ------------------------------------------------------------------ */
/* Driver: fork-join multi-stream schedule                             */
/* ------------------------------------------------------------------ */
extern "C" void kernel_launch(void* const* d_in, const int* in_sizes, int n_in,
                              void* d_out, int out_size)
{
    const float* x  = (const float*)d_in[0];
    const void*  ei = d_in[1];
    const float *wl[5], *wr[5], *aa[5], *bb[5];
    for (int i = 0; i < 5; i++) {
        wl[i] = (const float*)d_in[2 + 4 * i];
        wr[i] = (const float*)d_in[3 + 4 * i];
        aa[i] = (const float*)d_in[4 + 4 * i];
        bb[i] = (const float*)d_in[5 + 4 * i];
    }

    float* out       = (float*)d_out;
    float* out_recon = out;
    float* out_xrec  = out + (size_t)N_NODES * N_NODES;
    float* out_z     = out_xrec + (size_t)N_NODES * IN_CHN;

    float *xl, *xr, *h, *z, *re, *xd;
    cudaGetSymbolAddress((void**)&xl, g_xl);
    cudaGetSymbolAddress((void**)&xr, g_xr);
    cudaGetSymbolAddress((void**)&h,  g_h);
    cudaGetSymbolAddress((void**)&z,  g_z);
    cudaGetSymbolAddress((void**)&re, g_re);
    cudaGetSymbolAddress((void**)&xd, g_xd);

    cudaFuncSetAttribute(k_recon_mma2,
                         cudaFuncAttributeMaxDynamicSharedMemorySize, RC_SMEM);
    cudaFuncSetAttribute(k_gemm_dual_mma,
                         cudaFuncAttributeMaxDynamicSharedMemorySize, GD_SMEM);

    cudaStream_t s2 = g_res.s2;

    /* ---- fork: CSR build on s2, L1 GEMM on stream0 ---- */
    cudaEventRecord(g_res.ev_fork1, 0);
    cudaStreamWaitEvent(s2, g_res.ev_fork1, 0);

    k_pre0<<<1, 256, 0, s2>>>((const unsigned int*)ei);
    k_extract<<<(E_TOT + 255) / 256, 256, 0, s2>>>(ei);
    k_scan<<<1, 256, 0, s2>>>();
    k_scatter<<<(E_TOT + 255) / 256, 256, 0, s2>>>();
    cudaEventRecord(g_res.ev_csr, s2);

    k_gemm_dual_mma<<<dim3(N_NODES / 128, CHN / 64), 256, GD_SMEM>>>(x, wl[0], wr[0], xl, xr, IN_CHN, CHN);

    /* join: agg needs both CSR and L1 GEMM */
    cudaStreamWaitEvent(0, g_res.ev_csr, 0);
    k_agg2<1, 1><<<N_NODES / 4, 256>>>(xl, xr, aa[0], bb[0], h, (float*)0);

    /* ---- layer 2: h[.,128] -> z[.,256] (dual store: g_z + out_z) ---- */
    k_gemm_dual_mma<<<dim3(N_NODES / 128, 2 * CHN / 64), 256, GD_SMEM>>>(h, wl[1], wr[1], xl, xr, CHN, 2 * CHN);
    k_agg2<2, 0><<<N_NODES / 4, 256>>>(xl, xr, aa[1], bb[1], z, out_z);

    /* ---- layer 3: z[.,256] -> re[.,128] ---- */
    k_gemm_dual_mma<<<dim3(N_NODES / 128, CHN / 64), 256, GD_SMEM>>>(z, wl[2], wr[2], xl, xr, 2 * CHN, CHN);
    k_agg2<1, 1><<<N_NODES / 4, 256>>>(xl, xr, aa[2], bb[2], re, (float*)0);

    /* ---- fork: recon on s2, layers 4+5 on stream0 ---- */
    cudaEventRecord(g_res.ev_fork2, 0);
    cudaStreamWaitEvent(s2, g_res.ev_fork2, 0);
    k_recon_mma2<<<RC_NT, 256, RC_SMEM, s2>>>(re, out_recon);
    cudaEventRecord(g_res.ev_recon, s2);

    /* ---- layer 4: z[.,256] -> xd[.,128] ---- */
    k_gemm_dual_mma<<<dim3(N_NODES / 128, CHN / 64), 256, GD_SMEM>>>(z, wl[3], wr[3], xl, xr, 2 * CHN, CHN);
    k_agg2<1, 1><<<N_NODES / 4, 256>>>(xl, xr, aa[3], bb[3], xd, (float*)0);

    /* ---- layer 5: xd[.,128] -> x_rec[.,256] (directly into d_out) ---- */
    k_gemm_dual_mma<<<dim3(N_NODES / 128, IN_CHN / 64), 256, GD_SMEM>>>(xd, wl[4], wr[4], xl, xr, CHN, IN_CHN);
    k_agg2<2, 0><<<N_NODES / 4, 256>>>(xl, xr, aa[4], bb[4], out_xrec, (float*)0);

    /* join recon back into stream0 before returning */
    cudaStreamWaitEvent(0, g_res.ev_recon, 0);
}

// round 16
// speedup vs baseline: 1.0205x; 1.0205x over previous
#include <cuda_runtime.h>
#include <math.h>
#include <stdint.h>

#define N_NODES 8192
#define E_RAW   262144
#define E_TOT   (E_RAW + N_NODES)   /* 270336: edges + self loops */
#define IN_CHN  256
#define CHN     128
#define SLOPE   0.2f

/* ------------------------------------------------------------------ */
/* Device scratch (static — no allocation allowed)                     */
/* ------------------------------------------------------------------ */
__device__ int   g_nonzero;                 /* dtype detect flag        */
__device__ int   g_deg[N_NODES];
__device__ int   g_off[N_NODES + 1];
__device__ int   g_cursor[N_NODES];
__device__ int   g_srcraw[E_TOT];
__device__ int   g_dstraw[E_TOT];
__device__ int   g_srcsort[E_TOT];          /* src ids sorted by dst    */

__device__ float g_xl[N_NODES * 256];
__device__ float g_xr[N_NODES * 256];
__device__ float g_h [N_NODES * CHN];
__device__ float g_z [N_NODES * 2 * CHN];
__device__ float g_re[N_NODES * CHN];
__device__ float g_xd[N_NODES * CHN];

/* ------------------------------------------------------------------ */
/* Host-side stream/event resources (static init; host objects only)   */
/* ------------------------------------------------------------------ */
struct GpuRes {
    cudaStream_t s2;
    cudaEvent_t  ev_fork1, ev_csr, ev_fork2, ev_recon;
    GpuRes() {
        cudaStreamCreateWithFlags(&s2, cudaStreamNonBlocking);
        cudaEventCreateWithFlags(&ev_fork1, cudaEventDisableTiming);
        cudaEventCreateWithFlags(&ev_csr,   cudaEventDisableTiming);
        cudaEventCreateWithFlags(&ev_fork2, cudaEventDisableTiming);
        cudaEventCreateWithFlags(&ev_recon, cudaEventDisableTiming);
    }
};
static GpuRes g_res;

/* ------------------------------------------------------------------ */
/* mma.sync helpers                                                    */
/* ------------------------------------------------------------------ */
__device__ __forceinline__ uint32_t cvt_tf32(float x)
{
    uint32_t o;
    asm("cvt.rna.tf32.f32 %0, %1;" : "=r"(o) : "f"(x));
    return o;
}

__device__ __forceinline__ void mma_tf32(float* d,
                                         const uint32_t* a,
                                         const uint32_t* b)
{
    asm volatile(
        "mma.sync.aligned.m16n8k8.row.col.f32.tf32.tf32.f32 "
        "{%0,%1,%2,%3}, {%4,%5,%6,%7}, {%8,%9}, {%0,%1,%2,%3};"
        : "+f"(d[0]), "+f"(d[1]), "+f"(d[2]), "+f"(d[3])
        : "r"(a[0]), "r"(a[1]), "r"(a[2]), "r"(a[3]),
          "r"(b[0]), "r"(b[1]));
}

/* ------------------------------------------------------------------ */
/* Preprocessing: CSR build                                            */
/* ------------------------------------------------------------------ */
__global__ void k_pre0(const unsigned int* w)
{
    int t = threadIdx.x;              /* 256 threads */
    if (t == 0) g_nonzero = 0;
#pragma unroll
    for (int i = 0; i < 8; i++)
        *(int4*)(g_deg + t * 32 + i * 4) = make_int4(0, 0, 0, 0);
    __syncthreads();
    unsigned acc = 0;
#pragma unroll
    for (int i = 0; i < 16; i++)
        acc |= w[2 * (t * 16 + i) + 1];
    if (acc) atomicOr(&g_nonzero, 1);
}

__global__ void k_extract(const void* ei_raw)
{
    int i = blockIdx.x * blockDim.x + threadIdx.x;
    if (i >= E_TOT) return;
    int s, d;
    if (i < E_RAW) {
        if (g_nonzero == 0) {   /* int64 */
            const long long* e = (const long long*)ei_raw;
            s = (int)e[i];
            d = (int)e[E_RAW + i];
        } else {                /* int32 */
            const int* e = (const int*)ei_raw;
            s = e[i];
            d = e[E_RAW + i];
        }
    } else {                    /* self loop */
        s = i - E_RAW;
        d = s;
    }
    g_srcraw[i] = s;
    g_dstraw[i] = d;
    atomicAdd(&g_deg[d], 1);
}

/* 1 block x 256 threads; warp-shuffle scan */
__global__ void k_scan()
{
    __shared__ int ws[8];
    int t = threadIdx.x;
    int lane = t & 31, w = t >> 5;

    int4 loc[8];
    int sum = 0;
#pragma unroll
    for (int i = 0; i < 8; i++) {
        loc[i] = *(const int4*)(g_deg + t * 32 + i * 4);
        sum += loc[i].x + loc[i].y + loc[i].z + loc[i].w;
    }
    int inc = sum;
#pragma unroll
    for (int o = 1; o < 32; o <<= 1) {
        int v = __shfl_up_sync(0xffffffffu, inc, o);
        if (lane >= o) inc += v;
    }
    if (lane == 31) ws[w] = inc;
    __syncthreads();
    if (w == 0) {
        int x = (lane < 8) ? ws[lane] : 0;
#pragma unroll
        for (int o = 1; o < 8; o <<= 1) {
            int v = __shfl_up_sync(0xffffffffu, x, o);
            if (lane >= o) x += v;
        }
        if (lane < 8) ws[lane] = x;
    }
    __syncthreads();

    int run = inc - sum + (w > 0 ? ws[w - 1] : 0);
#pragma unroll
    for (int i = 0; i < 8; i++) {
        int4 d = loc[i];
        int4 o;
        o.x = run;            run += d.x;
        o.y = run;            run += d.y;
        o.z = run;            run += d.z;
        o.w = run;            run += d.w;
        *(int4*)(g_off    + t * 32 + i * 4) = o;
        *(int4*)(g_cursor + t * 32 + i * 4) = o;
    }
    if (t == 255) g_off[N_NODES] = ws[7];
}

__global__ void k_scatter()
{
    int i = blockIdx.x * blockDim.x + threadIdx.x;
    if (i >= E_TOT) return;
    int d = g_dstraw[i];
    int p = atomicAdd(&g_cursor[d], 1);
    g_srcsort[p] = g_srcraw[i];
}

/* ------------------------------------------------------------------ */
/* Dual GEMM via mma.sync tf32 + 3xTF32 compensation (fp32 accuracy).  */
/* CTA tile 128(M) x 32(N), K chunked by 64. 2 CTAs/SM (104KB smem).   */
/* ------------------------------------------------------------------ */
#define GS 68
#define GD_SMEM (384 * GS * 4)       /* A hi/lo (2x128) + B hi/lo (4x32) */

__global__ void __launch_bounds__(256, 2)
k_gemm_dual_mma(const float* __restrict__ X,
                const float* __restrict__ Wl,
                const float* __restrict__ Wr,
                float* __restrict__ XL,
                float* __restrict__ XR,
                int K, int OC)
{
    extern __shared__ float sm[];
    float* Ah  = sm;
    float* Al  = Ah  + 128 * GS;
    float* Blh = Al  + 128 * GS;
    float* Bll = Blh + 32 * GS;
    float* Brh = Bll + 32 * GS;
    float* Brl = Brh + 32 * GS;

    int tid = threadIdx.x;
    int wid = tid >> 5, lane = tid & 31;
    int m0 = blockIdx.x * 128, n0 = blockIdx.y * 32;
    int wm = (wid & 3) * 32;
    int wn = (wid >> 2) * 16;        /* 2 warps cover 32 cols, 16 each */
    int fr = lane >> 2, fc = lane & 3;

    float accL[2][2][4], accR[2][2][4];
#pragma unroll
    for (int mt = 0; mt < 2; mt++)
#pragma unroll
        for (int nt = 0; nt < 2; nt++)
#pragma unroll
            for (int e = 0; e < 4; e++) { accL[mt][nt][e] = 0.0f; accR[mt][nt][e] = 0.0f; }

    for (int k0 = 0; k0 < K; k0 += 64) {
        /* A chunk: 128 rows x 64 cols */
#pragma unroll
        for (int it = 0; it < 8; it++) {
            int f = it * 256 + tid;
            int r = f >> 4, q = f & 15;
            float4 v = *(const float4*)(X + (size_t)(m0 + r) * K + k0 + q * 4);
            uint32_t h0 = cvt_tf32(v.x), h1 = cvt_tf32(v.y);
            uint32_t h2 = cvt_tf32(v.z), h3 = cvt_tf32(v.w);
            uint32_t* dh = (uint32_t*)(Ah + r * GS + q * 4);
            uint32_t* dl = (uint32_t*)(Al + r * GS + q * 4);
            dh[0] = h0; dh[1] = h1; dh[2] = h2; dh[3] = h3;
            dl[0] = cvt_tf32(v.x - __uint_as_float(h0));
            dl[1] = cvt_tf32(v.y - __uint_as_float(h1));
            dl[2] = cvt_tf32(v.z - __uint_as_float(h2));
            dl[3] = cvt_tf32(v.w - __uint_as_float(h3));
        }
        /* B chunks: 32 rows x 64 cols each */
#pragma unroll
        for (int it = 0; it < 2; it++) {
            int f = it * 256 + tid;
            int r = f >> 4, q = f & 15;
            float4 v = *(const float4*)(Wl + (size_t)(n0 + r) * K + k0 + q * 4);
            uint32_t h0 = cvt_tf32(v.x), h1 = cvt_tf32(v.y);
            uint32_t h2 = cvt_tf32(v.z), h3 = cvt_tf32(v.w);
            uint32_t* dh = (uint32_t*)(Blh + r * GS + q * 4);
            uint32_t* dl = (uint32_t*)(Bll + r * GS + q * 4);
            dh[0] = h0; dh[1] = h1; dh[2] = h2; dh[3] = h3;
            dl[0] = cvt_tf32(v.x - __uint_as_float(h0));
            dl[1] = cvt_tf32(v.y - __uint_as_float(h1));
            dl[2] = cvt_tf32(v.z - __uint_as_float(h2));
            dl[3] = cvt_tf32(v.w - __uint_as_float(h3));

            v = *(const float4*)(Wr + (size_t)(n0 + r) * K + k0 + q * 4);
            h0 = cvt_tf32(v.x); h1 = cvt_tf32(v.y);
            h2 = cvt_tf32(v.z); h3 = cvt_tf32(v.w);
            dh = (uint32_t*)(Brh + r * GS + q * 4);
            dl = (uint32_t*)(Brl + r * GS + q * 4);
            dh[0] = h0; dh[1] = h1; dh[2] = h2; dh[3] = h3;
            dl[0] = cvt_tf32(v.x - __uint_as_float(h0));
            dl[1] = cvt_tf32(v.y - __uint_as_float(h1));
            dl[2] = cvt_tf32(v.z - __uint_as_float(h2));
            dl[3] = cvt_tf32(v.w - __uint_as_float(h3));
        }
        __syncthreads();

        const uint32_t* Ahu  = (const uint32_t*)Ah;
        const uint32_t* Alu  = (const uint32_t*)Al;
        const uint32_t* Blhu = (const uint32_t*)Blh;
        const uint32_t* Bllu = (const uint32_t*)Bll;
        const uint32_t* Brhu = (const uint32_t*)Brh;
        const uint32_t* Brlu = (const uint32_t*)Brl;

#pragma unroll
        for (int ks = 0; ks < 64; ks += 8) {
            uint32_t ah[2][4], al[2][4];
#pragma unroll
            for (int mt = 0; mt < 2; mt++) {
                int row = wm + mt * 16 + fr;
                ah[mt][0] = Ahu[row * GS + ks + fc];
                ah[mt][1] = Ahu[(row + 8) * GS + ks + fc];
                ah[mt][2] = Ahu[row * GS + ks + 4 + fc];
                ah[mt][3] = Ahu[(row + 8) * GS + ks + 4 + fc];
                al[mt][0] = Alu[row * GS + ks + fc];
                al[mt][1] = Alu[(row + 8) * GS + ks + fc];
                al[mt][2] = Alu[row * GS + ks + 4 + fc];
                al[mt][3] = Alu[(row + 8) * GS + ks + 4 + fc];
            }
            uint32_t blh[2][2], bll[2][2], brh[2][2], brl[2][2];
#pragma unroll
            for (int nt = 0; nt < 2; nt++) {
                int n = wn + nt * 8 + fr;
                blh[nt][0] = Blhu[n * GS + ks + fc];
                blh[nt][1] = Blhu[n * GS + ks + 4 + fc];
                bll[nt][0] = Bllu[n * GS + ks + fc];
                bll[nt][1] = Bllu[n * GS + ks + 4 + fc];
                brh[nt][0] = Brhu[n * GS + ks + fc];
                brh[nt][1] = Brhu[n * GS + ks + 4 + fc];
                brl[nt][0] = Brlu[n * GS + ks + fc];
                brl[nt][1] = Brlu[n * GS + ks + 4 + fc];
            }
#pragma unroll
            for (int mt = 0; mt < 2; mt++)
#pragma unroll
                for (int nt = 0; nt < 2; nt++) {
                    mma_tf32(accL[mt][nt], al[mt], blh[nt]);
                    mma_tf32(accL[mt][nt], ah[mt], bll[nt]);
                    mma_tf32(accL[mt][nt], ah[mt], blh[nt]);
                    mma_tf32(accR[mt][nt], al[mt], brh[nt]);
                    mma_tf32(accR[mt][nt], ah[mt], brl[nt]);
                    mma_tf32(accR[mt][nt], ah[mt], brh[nt]);
                }
        }
        __syncthreads();
    }

#pragma unroll
    for (int mt = 0; mt < 2; mt++)
#pragma unroll
        for (int nt = 0; nt < 2; nt++) {
            int row = m0 + wm + mt * 16 + fr;
            int col = n0 + wn + nt * 8 + (lane & 3) * 2;
            float* cL = accL[mt][nt];
            float* cR = accR[mt][nt];
            XL[(size_t)row * OC + col]           = cL[0];
            XL[(size_t)row * OC + col + 1]       = cL[1];
            XL[(size_t)(row + 8) * OC + col]     = cL[2];
            XL[(size_t)(row + 8) * OC + col + 1] = cL[3];
            XR[(size_t)row * OC + col]           = cR[0];
            XR[(size_t)row * OC + col + 1]       = cR[1];
            XR[(size_t)(row + 8) * OC + col]     = cR[2];
            XR[(size_t)(row + 8) * OC + col + 1] = cR[3];
        }
}

/* ------------------------------------------------------------------ */
/* GATv2 aggregation (R14 proven): warp/node, float4 gathers, 4-edge   */
/* batches; ping-pong for NC=1 only.                                   */
/* ------------------------------------------------------------------ */
__device__ __forceinline__ float warp_sum(float p)
{
#pragma unroll
    for (int o = 16; o > 0; o >>= 1) p += __shfl_xor_sync(0xffffffffu, p, o);
    return p;
}

template <int NC, int PIPE>
__global__ void k_agg(const float* __restrict__ XL,
                      const float* __restrict__ XR,
                      const float* __restrict__ att,
                      const float* __restrict__ bias,
                      float* __restrict__ out,
                      float* __restrict__ out2)
{
    const int OC4 = NC * 32;
    int warp = threadIdx.x >> 5, lane = threadIdx.x & 31;
    int v = blockIdx.x * 8 + warp;

    const float4* XL4 = (const float4*)XL;
    const float4* XR4 = (const float4*)XR;
    const float4* at4 = (const float4*)att;
    const float4* bi4 = (const float4*)bias;

    float4 xrv[NC], atv[NC], acc[NC];
#pragma unroll
    for (int c = 0; c < NC; c++) {
        xrv[c] = XR4[v * OC4 + c * 32 + lane];
        atv[c] = at4[c * 32 + lane];
        acc[c] = make_float4(0.f, 0.f, 0.f, 0.f);
    }

    float m = -3.0e38f, s = 0.0f;
    int e0 = g_off[v], e1 = g_off[v + 1];
    int n4 = (e1 - e0) >> 2;

#define LK(t) ((t) > 0.0f ? (t) : SLOPE * (t))
#define DOT1(p, xv, c)                                                      \
    { float t;                                                              \
      t = xv.x + xrv[c].x; p += atv[c].x * LK(t);                           \
      t = xv.y + xrv[c].y; p += atv[c].y * LK(t);                           \
      t = xv.z + xrv[c].z; p += atv[c].z * LK(t);                           \
      t = xv.w + xrv[c].w; p += atv[c].w * LK(t); }

#define LOADB(X, base)                                                      \
    { int u0 = g_srcsort[(base)],     u1 = g_srcsort[(base) + 1];           \
      int u2 = g_srcsort[(base) + 2], u3 = g_srcsort[(base) + 3];           \
      _Pragma("unroll")                                                     \
      for (int c = 0; c < NC; c++) {                                        \
          X[0][c] = XL4[(size_t)u0 * OC4 + c * 32 + lane];                  \
          X[1][c] = XL4[(size_t)u1 * OC4 + c * 32 + lane];                  \
          X[2][c] = XL4[(size_t)u2 * OC4 + c * 32 + lane];                  \
          X[3][c] = XL4[(size_t)u3 * OC4 + c * 32 + lane];                  \
      } }

#define PROCB(X)                                                            \
    { float p0 = 0.f, p1 = 0.f, p2 = 0.f, p3 = 0.f;                         \
      _Pragma("unroll")                                                     \
      for (int c = 0; c < NC; c++) {                                        \
          DOT1(p0, X[0][c], c); DOT1(p1, X[1][c], c);                       \
          DOT1(p2, X[2][c], c); DOT1(p3, X[3][c], c);                       \
      }                                                                     \
      p0 = warp_sum(p0); p1 = warp_sum(p1);                                 \
      p2 = warp_sum(p2); p3 = warp_sum(p3);                                 \
      float bm = fmaxf(fmaxf(p0, p1), fmaxf(p2, p3));                       \
      float mn = fmaxf(m, bm);                                              \
      float sc = __expf(m - mn);                                            \
      float w0 = __expf(p0 - mn), w1 = __expf(p1 - mn);                     \
      float w2 = __expf(p2 - mn), w3 = __expf(p3 - mn);                     \
      s = s * sc + ((w0 + w1) + (w2 + w3));                                 \
      _Pragma("unroll")                                                     \
      for (int c = 0; c < NC; c++) {                                        \
          acc[c].x = acc[c].x * sc + w0 * X[0][c].x + w1 * X[1][c].x        \
                                   + w2 * X[2][c].x + w3 * X[3][c].x;       \
          acc[c].y = acc[c].y * sc + w0 * X[0][c].y + w1 * X[1][c].y        \
                                   + w2 * X[2][c].y + w3 * X[3][c].y;       \
          acc[c].z = acc[c].z * sc + w0 * X[0][c].z + w1 * X[1][c].z        \
                                   + w2 * X[2][c].z + w3 * X[3][c].z;       \
          acc[c].w = acc[c].w * sc + w0 * X[0][c].w + w1 * X[1][c].w        \
                                   + w2 * X[2][c].w + w3 * X[3][c].w;       \
      }                                                                     \
      m = mn; }

    if (PIPE) {
        float4 xA[4][NC], xB[4][NC];
        int b = 0;
        if (n4 > 0) LOADB(xA, e0);
        while (b < n4) {
            if (b + 1 < n4) LOADB(xB, e0 + (b + 1) * 4);
            PROCB(xA);
            b++;
            if (b >= n4) break;
            if (b + 1 < n4) LOADB(xA, e0 + (b + 1) * 4);
            PROCB(xB);
            b++;
        }
    } else {
        float4 xA[4][NC];
        for (int b = 0; b < n4; b++) {
            LOADB(xA, e0 + b * 4);
            PROCB(xA);
        }
    }

    for (int e = e0 + n4 * 4; e < e1; e++) {
        int u = g_srcsort[e];
        float4 xv[NC];
        float p = 0.f;
#pragma unroll
        for (int c = 0; c < NC; c++) {
            xv[c] = XL4[(size_t)u * OC4 + c * 32 + lane];
            DOT1(p, xv[c], c);
        }
        p = warp_sum(p);
        float mn = fmaxf(m, p);
        float sc = __expf(m - mn);
        float w  = __expf(p - mn);
        s = s * sc + w;
#pragma unroll
        for (int c = 0; c < NC; c++) {
            acc[c].x = acc[c].x * sc + w * xv[c].x;
            acc[c].y = acc[c].y * sc + w * xv[c].y;
            acc[c].z = acc[c].z * sc + w * xv[c].z;
            acc[c].w = acc[c].w * sc + w * xv[c].w;
        }
        m = mn;
    }
#undef DOT1
#undef LK
#undef LOADB
#undef PROCB

    float inv = 1.0f / s;
#pragma unroll
    for (int c = 0; c < NC; c++) {
        float4 b4 = bi4[c * 32 + lane];
        float4 o;
        o.x = fmaxf(acc[c].x * inv + b4.x, 0.0f);
        o.y = fmaxf(acc[c].y * inv + b4.y, 0.0f);
        o.z = fmaxf(acc[c].z * inv + b4.z, 0.0f);
        o.w = fmaxf(acc[c].w * inv + b4.w, 0.0f);
        ((float4*)out)[v * OC4 + c * 32 + lane] = o;
        if (out2) ((float4*)out2)[v * OC4 + c * 32 + lane] = o;
    }
}

/* ------------------------------------------------------------------ */
/* recon = sigmoid(R @ R^T) via mma.sync tf32. 128x64 tiles, 4160     */
/* CTAs, 2 CTAs/SM. Dual-staged epilogue.                              */
/* ------------------------------------------------------------------ */
#define RSR      132
#define RC_SMEM  ((128 + 64) * RSR * 4)    /* 101376 bytes */
#define RC_NT    4160

__global__ void __launch_bounds__(256, 2)
k_recon_mma2(const float* __restrict__ R, float* __restrict__ O)
{
    extern __shared__ float smf[];
    float* As  = smf;
    float* Bs  = smf + 128 * RSR;
    float* Cs1 = As;
    float* Cs2 = Bs;

    int tid = threadIdx.x;
    int wid = tid >> 5, lane = tid & 31;

    int t = blockIdx.x;
    int p = t >> 1, hh = t & 1;
    int bj = (int)((sqrtf(8.0f * (float)p + 1.0f) - 1.0f) * 0.5f);
    while ((bj + 1) * (bj + 2) / 2 <= p) bj++;
    while (bj * (bj + 1) / 2 > p) bj--;
    int bi = p - bj * (bj + 1) / 2;
    int m0 = bi * 128;
    int n0 = bj * 128 + hh * 64;

    {
        const float4* srcA = (const float4*)(R + (size_t)m0 * CHN);
        const float4* srcB = (const float4*)(R + (size_t)n0 * CHN);
#pragma unroll
        for (int it = 0; it < 16; it++) {
            int f = it * 256 + tid;
            int r = f >> 5, q = f & 31;
            float4 va = srcA[r * 32 + q];
            uint32_t* da = (uint32_t*)(As + r * RSR + q * 4);
            da[0] = cvt_tf32(va.x); da[1] = cvt_tf32(va.y);
            da[2] = cvt_tf32(va.z); da[3] = cvt_tf32(va.w);
        }
#pragma unroll
        for (int it = 0; it < 8; it++) {
            int f = it * 256 + tid;
            int r = f >> 5, q = f & 31;
            float4 vb = srcB[r * 32 + q];
            uint32_t* db = (uint32_t*)(Bs + r * RSR + q * 4);
            db[0] = cvt_tf32(vb.x); db[1] = cvt_tf32(vb.y);
            db[2] = cvt_tf32(vb.z); db[3] = cvt_tf32(vb.w);
        }
    }
    __syncthreads();

    int wm = (wid & 3) * 32;
    int wn = (wid >> 2) * 32;
    int fr = lane >> 2, fc = lane & 3;

    float acc[2][4][4];
#pragma unroll
    for (int mt = 0; mt < 2; mt++)
#pragma unroll
        for (int nt = 0; nt < 4; nt++)
#pragma unroll
            for (int e = 0; e < 4; e++) acc[mt][nt][e] = 0.0f;

    const uint32_t* Au = (const uint32_t*)As;
    const uint32_t* Bu = (const uint32_t*)Bs;

#pragma unroll
    for (int k0 = 0; k0 < 128; k0 += 8) {
        uint32_t af[2][4];
#pragma unroll
        for (int mt = 0; mt < 2; mt++) {
            int row = wm + mt * 16 + fr;
            af[mt][0] = Au[row * RSR + k0 + fc];
            af[mt][1] = Au[(row + 8) * RSR + k0 + fc];
            af[mt][2] = Au[row * RSR + k0 + 4 + fc];
            af[mt][3] = Au[(row + 8) * RSR + k0 + 4 + fc];
        }
        uint32_t bf[4][2];
#pragma unroll
        for (int nt = 0; nt < 4; nt++) {
            int n = wn + nt * 8 + fr;
            bf[nt][0] = Bu[n * RSR + k0 + fc];
            bf[nt][1] = Bu[n * RSR + k0 + 4 + fc];
        }
#pragma unroll
        for (int mt = 0; mt < 2; mt++)
#pragma unroll
            for (int nt = 0; nt < 4; nt++)
                mma_tf32(acc[mt][nt], af[mt], bf[nt]);
    }
    __syncthreads();

#pragma unroll
    for (int mt = 0; mt < 2; mt++)
#pragma unroll
        for (int nt = 0; nt < 4; nt++) {
            int row = wm + mt * 16 + fr;
            int col = wn + nt * 8 + fc * 2;
            float* c = acc[mt][nt];
            float s0 = 1.0f / (1.0f + __expf(-c[0]));
            float s1 = 1.0f / (1.0f + __expf(-c[1]));
            float s2 = 1.0f / (1.0f + __expf(-c[2]));
            float s3 = 1.0f / (1.0f + __expf(-c[3]));
            Cs1[row * RSR + col]           = s0;
            Cs1[row * RSR + col + 1]       = s1;
            Cs1[(row + 8) * RSR + col]     = s2;
            Cs1[(row + 8) * RSR + col + 1] = s3;
            Cs2[col * RSR + row]           = s0;
            Cs2[(col + 1) * RSR + row]     = s1;
            Cs2[col * RSR + row + 8]       = s2;
            Cs2[(col + 1) * RSR + row + 8] = s3;
        }
    __syncthreads();

    {
        int c4 = (tid & 15) * 4;
        int r0 = tid >> 4;
#pragma unroll
        for (int r = r0; r < 128; r += 16) {
            float4 v = *(const float4*)(Cs1 + r * RSR + c4);
            *(float4*)(O + (size_t)(m0 + r) * N_NODES + n0 + c4) = v;
        }
    }
    {
        int c4 = (tid & 31) * 4;
        int r0 = tid >> 5;
#pragma unroll
        for (int r = r0; r < 64; r += 8) {
            float4 v = *(const float4*)(Cs2 + r * RSR + c4);
            *(float4*)(O + (size_t)(n0 + r) * N_NODES + m0 + c4) = v;
        }
    }
}

/* ------------------------------------------------------------------ */
/* Driver: fork-join multi-stream schedule                             */
/* ------------------------------------------------------------------ */
extern "C" void kernel_launch(void* const* d_in, const int* in_sizes, int n_in,
                              void* d_out, int out_size)
{
    const float* x  = (const float*)d_in[0];
    const void*  ei = d_in[1];
    const float *wl[5], *wr[5], *aa[5], *bb[5];
    for (int i = 0; i < 5; i++) {
        wl[i] = (const float*)d_in[2 + 4 * i];
        wr[i] = (const float*)d_in[3 + 4 * i];
        aa[i] = (const float*)d_in[4 + 4 * i];
        bb[i] = (const float*)d_in[5 + 4 * i];
    }

    float* out       = (float*)d_out;
    float* out_recon = out;
    float* out_xrec  = out + (size_t)N_NODES * N_NODES;
    float* out_z     = out_xrec + (size_t)N_NODES * IN_CHN;

    float *xl, *xr, *h, *z, *re, *xd;
    cudaGetSymbolAddress((void**)&xl, g_xl);
    cudaGetSymbolAddress((void**)&xr, g_xr);
    cudaGetSymbolAddress((void**)&h,  g_h);
    cudaGetSymbolAddress((void**)&z,  g_z);
    cudaGetSymbolAddress((void**)&re, g_re);
    cudaGetSymbolAddress((void**)&xd, g_xd);

    cudaFuncSetAttribute(k_recon_mma2,
                         cudaFuncAttributeMaxDynamicSharedMemorySize, RC_SMEM);
    cudaFuncSetAttribute(k_gemm_dual_mma,
                         cudaFuncAttributeMaxDynamicSharedMemorySize, GD_SMEM);

    cudaStream_t s2 = g_res.s2;

    /* ---- fork: CSR build on s2, L1 GEMM on stream0 ---- */
    cudaEventRecord(g_res.ev_fork1, 0);
    cudaStreamWaitEvent(s2, g_res.ev_fork1, 0);

    k_pre0<<<1, 256, 0, s2>>>((const unsigned int*)ei);
    k_extract<<<(E_TOT + 255) / 256, 256, 0, s2>>>(ei);
    k_scan<<<1, 256, 0, s2>>>();
    k_scatter<<<(E_TOT + 255) / 256, 256, 0, s2>>>();
    cudaEventRecord(g_res.ev_csr, s2);

    k_gemm_dual_mma<<<dim3(N_NODES / 128, CHN / 32), 256, GD_SMEM>>>(x, wl[0], wr[0], xl, xr, IN_CHN, CHN);

    /* join: agg needs both CSR and L1 GEMM */
    cudaStreamWaitEvent(0, g_res.ev_csr, 0);
    k_agg<1, 1><<<N_NODES / 8, 256>>>(xl, xr, aa[0], bb[0], h, (float*)0);

    /* ---- layer 2: h[.,128] -> z[.,256] (dual store: g_z + out_z) ---- */
    k_gemm_dual_mma<<<dim3(N_NODES / 128, 2 * CHN / 32), 256, GD_SMEM>>>(h, wl[1], wr[1], xl, xr, CHN, 2 * CHN);
    k_agg<2, 0><<<N_NODES / 8, 256>>>(xl, xr, aa[1], bb[1], z, out_z);

    /* ---- layer 3: z[.,256] -> re[.,128] ---- */
    k_gemm_dual_mma<<<dim3(N_NODES / 128, CHN / 32), 256, GD_SMEM>>>(z, wl[2], wr[2], xl, xr, 2 * CHN, CHN);
    k_agg<1, 1><<<N_NODES / 8, 256>>>(xl, xr, aa[2], bb[2], re, (float*)0);

    /* ---- fork: recon on s2, layers 4+5 on stream0 ---- */
    cudaEventRecord(g_res.ev_fork2, 0);
    cudaStreamWaitEvent(s2, g_res.ev_fork2, 0);
    k_recon_mma2<<<RC_NT, 256, RC_SMEM, s2>>>(re, out_recon);
    cudaEventRecord(g_res.ev_recon, s2);

    /* ---- layer 4: z[.,256] -> xd[.,128] ---- */
    k_gemm_dual_mma<<<dim3(N_NODES / 128, CHN / 32), 256, GD_SMEM>>>(z, wl[3], wr[3], xl, xr, 2 * CHN, CHN);
    k_agg<1, 1><<<N_NODES / 8, 256>>>(xl, xr, aa[3], bb[3], xd, (float*)0);

    /* ---- layer 5: xd[.,128] -> x_rec[.,256] (directly into d_out) ---- */
    k_gemm_dual_mma<<<dim3(N_NODES / 128, IN_CHN / 32), 256, GD_SMEM>>>(xd, wl[4], wr[4], xl, xr, CHN, IN_CHN);
    k_agg<2, 0><<<N_NODES / 8, 256>>>(xl, xr, aa[4], bb[4], out_xrec, (float*)0);

    /* join recon back into stream0 before returning */
    cudaStreamWaitEvent(0, g_res.ev_recon, 0);
}